// round 10
// baseline (speedup 1.0000x reference)
#include <cuda_runtime.h>
#include <cuda_fp16.h>
#include <math.h>
#include <stdint.h>

#define HD 512
#define PD 256
#define LD 4096
#define BSZ 8
#define MROWS (BSZ*LD)      // 32768
#define CH 64
#define NCH (LD/CH)         // 64

// ---- device scratch (no allocation allowed) ----
__device__ __align__(16) float g_Bu[(size_t)MROWS*HD];        // 64 MB fp32
__device__ __align__(16) __half g_Ah[(size_t)MROWS*HD];       // 32 MB [m][k]
__device__ __align__(16) __half g_W1h[HD*HD];                 // [n][k] fp16
__device__ __align__(16) __half g_W2h[HD*HD];
__device__ float2 g_lambda[PD];
__device__ float2 g_lamS[PD];
__device__ float2 g_coef[PD];
__device__ float2 g_bout [BSZ*NCH*PD];
__device__ float2 g_carry[BSZ*NCH*PD];

// ---- PTX helpers ----
__device__ __forceinline__ uint32_t s2u(const void* p) {
    uint32_t a;
    asm("{ .reg .u64 t; cvta.to.shared.u64 t, %1; cvt.u32.u64 %0, t; }" : "=r"(a) : "l"(p));
    return a;
}
__device__ __forceinline__ void cp16(uint32_t dst, const void* src) {
    asm volatile("cp.async.cg.shared.global [%0], [%1], 16;" :: "r"(dst), "l"(src) : "memory");
}
__device__ __forceinline__ void ldm_x4(uint32_t* r, uint32_t addr) {
    asm volatile("ldmatrix.sync.aligned.m8n8.x4.shared.b16 {%0,%1,%2,%3}, [%4];"
                 : "=r"(r[0]), "=r"(r[1]), "=r"(r[2]), "=r"(r[3]) : "r"(addr));
}
__device__ __forceinline__ void mma16816(float* d, const uint32_t* a, uint32_t b0, uint32_t b1) {
    asm volatile("mma.sync.aligned.m16n8k16.row.col.f32.f16.f16.f32 "
                 "{%0,%1,%2,%3}, {%4,%5,%6,%7}, {%8,%9}, {%0,%1,%2,%3};"
                 : "+f"(d[0]), "+f"(d[1]), "+f"(d[2]), "+f"(d[3])
                 : "r"(a[0]), "r"(a[1]), "r"(a[2]), "r"(a[3]), "r"(b0), "r"(b1));
}

// ---- prep: discretization ----
__global__ void prep1_kernel(const float* __restrict__ Lre,
                             const float* __restrict__ Lim,
                             const float* __restrict__ logstep) {
    int p = threadIdx.x;
    if (p >= PD) return;
    double lre = (double)Lre[p], lim = (double)Lim[p];
    double st  = exp((double)logstep[p]);
    double ar = lre * st, ai = lim * st;
    double er = exp(ar);
    double lr = er * cos(ai), li = er * sin(ai);
    g_lambda[p] = make_float2((float)lr, (float)li);
    double eS = exp(ar * (double)CH);
    g_lamS[p]  = make_float2((float)(eS * cos(ai * (double)CH)),
                             (float)(eS * sin(ai * (double)CH)));
    double nr = lr - 1.0, ni = li;
    double d2 = lre * lre + lim * lim;
    g_coef[p] = make_float2((float)((nr * lre + ni * lim) / d2),
                            (float)((ni * lre - nr * lim) / d2));
}

// weight assembly: directly write transposed fp16 [n][k]
__global__ void prep2_kernel(const float* __restrict__ B,
                             const float* __restrict__ C) {
    int tot = HD * HD;
    for (int idx = blockIdx.x * blockDim.x + threadIdx.x;
         idx < 2 * tot; idx += gridDim.x * blockDim.x) {
        if (idx < tot) {
            int n = idx >> 9, k = idx & 511;
            int p = n >> 1;
            float2 c = g_coef[p];
            float b0 = B[((size_t)p * HD + k) * 2 + 0];
            float b1 = B[((size_t)p * HD + k) * 2 + 1];
            float v = (n & 1) ? fmaf(c.x, b1,  c.y * b0)
                              : fmaf(c.x, b0, -c.y * b1);
            g_W1h[n * 512 + k] = __float2half_rn(v);
        } else {
            int j = idx - tot;
            int n = j >> 9, k = j & 511;
            int p = k >> 1;
            float cv = C[((size_t)n * PD + p) * 2 + (k & 1)];
            float v = (k & 1) ? (-2.0f * cv) : (2.0f * cv);
            g_W2h[n * 512 + k] = __float2half_rn(v);
        }
    }
}

// x fp32 -> Ah fp16 row-major
__global__ void convx_kernel(const float* __restrict__ x) {
    size_t nseg = (size_t)MROWS * 64;
    for (size_t g = (size_t)blockIdx.x * blockDim.x + threadIdx.x;
         g < nseg; g += (size_t)gridDim.x * blockDim.x) {
        size_t m = g >> 6; int k8 = (int)(g & 63);
        const float4* s4 = (const float4*)(x + m * 512 + k8 * 8);
        float4 a = s4[0], b = s4[1];
        __half2 h0 = __floats2half2_rn(a.x, a.y);
        __half2 h1 = __floats2half2_rn(a.z, a.w);
        __half2 h2 = __floats2half2_rn(b.x, b.y);
        __half2 h3 = __floats2half2_rn(b.z, b.w);
        *(uint4*)(g_Ah + m * 512 + k8 * 8) =
            make_uint4(*(uint32_t*)&h0, *(uint32_t*)&h1, *(uint32_t*)&h2, *(uint32_t*)&h3);
    }
}

// ---- chunked complex scan (pass 1 read-only) ----
__global__ void scan1_kernel() {
    int tid = blockIdx.x * 256 + threadIdx.x;
    int p = tid & (PD - 1);
    int c = (tid >> 8) & (NCH - 1);
    int b = tid >> 14;
    float2 lam = g_lambda[p];
    float xr = 0.f, xi = 0.f;
    const float2* base = (const float2*)g_Bu + ((size_t)(b * LD + c * CH)) * PD + p;
    #pragma unroll 8
    for (int j = 0; j < CH; j++) {
        float2 v = base[(size_t)j * PD];
        float nr = fmaf(lam.x, xr, fmaf(-lam.y, xi, v.x));
        float ni = fmaf(lam.y, xr, fmaf( lam.x, xi, v.y));
        xr = nr; xi = ni;
    }
    g_bout[(b * NCH + c) * PD + p] = make_float2(xr, xi);
}

__global__ void scan2_kernel() {
    int b = blockIdx.x;
    int p = threadIdx.x;
    float2 lS = g_lamS[p];
    float cr = 0.f, ci = 0.f;
    for (int c = 0; c < NCH; c++) {
        int idx = (b * NCH + c) * PD + p;
        g_carry[idx] = make_float2(cr, ci);
        float2 bo = g_bout[idx];
        float nr = fmaf(lS.x, cr, fmaf(-lS.y, ci, bo.x));
        float ni = fmaf(lS.y, cr, fmaf( lS.x, ci, bo.y));
        cr = nr; ci = ni;
    }
}

// re-run local recurrence from carry + fp16 convert of xs -> Ah
__global__ void convxs_kernel() {
    int tid = blockIdx.x * 256 + threadIdx.x;
    int p = tid & (PD - 1);
    int c = (tid >> 8) & (NCH - 1);
    int b = tid >> 14;
    float2 lam = g_lambda[p];
    float2 car = g_carry[(b * NCH + c) * PD + p];
    float tr = car.x, ti = car.y;
    const float2* src = (const float2*)g_Bu + ((size_t)(b * LD + c * CH)) * PD + p;
    size_t m0 = (size_t)b * LD + c * CH;
    #pragma unroll 4
    for (int j = 0; j < CH; j++) {
        float2 v = src[(size_t)j * PD];
        float nr = fmaf(lam.x, tr, fmaf(-lam.y, ti, v.x));
        float ni = fmaf(lam.y, tr, fmaf( lam.x, ti, v.y));
        tr = nr; ti = ni;
        __half2 H = __floats2half2_rn(tr, ti);
        *(uint32_t*)(g_Ah + (m0 + j) * 512 + 2 * p) = *(uint32_t*)&H;
    }
}

// ---- HMMA fp16 GEMM: C[128,64] per CTA, K = 512, BK = 64 ----
// 8 warps (4 in M x 2 in N), warp tile 32x32 -> 32 acc regs/thread
// MODE 0: g_Bu = x(Ah) @ W1h ; MODE 1: out = xs(Ah) @ W2h + D*x
#define NSTG 3
#define STGB 24576            // A 16KB + B 8KB per stage
#define GSMEM (NSTG*STGB)     // 72 KB
#define NITER 8               // 512 / 64

template <int MODE>
__global__ void __launch_bounds__(256, 3)
gemm_kernel(const float* __restrict__ skipX,
            float* __restrict__ Cext,
            const float* __restrict__ Dv) {
    extern __shared__ __align__(1024) unsigned char smem[];
    uint32_t sa = s2u(smem);
    int tid = threadIdx.x, wid = tid >> 5, lane = tid & 31;
    int row0 = blockIdx.y * 128, col0 = blockIdx.x * 64;
    float* Co = MODE ? Cext : g_Bu;
    const __half* Wh = MODE ? g_W2h : g_W1h;

    // loader: 16B chunk lc (0..7), base row lr (0..31)
    int lc = tid & 7, lr = tid >> 3;

    auto load_stage = [&](int st, int it) {
        int k0 = it * 64 + lc * 8;
        uint32_t sA = sa + st * STGB;
        uint32_t sB = sA + 16384;
        #pragma unroll
        for (int i = 0; i < 4; i++) {
            int r = lr + i * 32;
            cp16(sA + (uint32_t)(lc * 128 + r) * 16, g_Ah + (size_t)(row0 + r) * 512 + k0);
        }
        #pragma unroll
        for (int i = 0; i < 2; i++) {
            int r = lr + i * 32;
            cp16(sB + (uint32_t)(lc * 64 + r) * 16, Wh + (size_t)(col0 + r) * 512 + k0);
        }
        asm volatile("cp.async.commit_group;" ::: "memory");
    };

    float acc[2][4][4];
    #pragma unroll
    for (int i = 0; i < 2; i++)
        #pragma unroll
        for (int j = 0; j < 4; j++)
            #pragma unroll
            for (int q = 0; q < 4; q++) acc[i][j][q] = 0.f;

    load_stage(0, 0);
    load_stage(1, 1);

    int wm = (wid & 3) * 32, wn = (wid >> 2) * 32;
    int lrow = lane & 15, lhalf = lane >> 4;

    #pragma unroll 1
    for (int it = 0; it < NITER; it++) {
        int st = it % NSTG;
        asm volatile("cp.async.wait_group 1;" ::: "memory");
        __syncthreads();
        if (it + 2 < NITER) load_stage((it + 2) % NSTG, it + 2);
        else asm volatile("cp.async.commit_group;" ::: "memory");

        uint32_t sA = sa + st * STGB, sB = sA + 16384;
        #pragma unroll
        for (int s = 0; s < 4; s++) {
            int ch = s * 2 + lhalf;
            uint32_t a[2][4], b[2][4];
            #pragma unroll
            for (int tm = 0; tm < 2; tm++)
                ldm_x4(a[tm], sA + (uint32_t)(ch * 128 + wm + tm * 16 + lrow) * 16);
            #pragma unroll
            for (int tp = 0; tp < 2; tp++)
                ldm_x4(b[tp], sB + (uint32_t)(ch * 64 + wn + tp * 16 + lrow) * 16);
            #pragma unroll
            for (int tm = 0; tm < 2; tm++)
                #pragma unroll
                for (int tn = 0; tn < 4; tn++) {
                    int tp = tn >> 1, w = tn & 1;
                    mma16816(acc[tm][tn], a[tm], b[tp][w], b[tp][w + 2]);
                }
        }
    }

    // epilogue: d-frag lane mapping: rows l>>2 (+8), cols (l&3)*2 (+1)
    int rbase = row0 + wm + (lane >> 2);
    int nb0 = col0 + wn + (lane & 3) * 2;
    #pragma unroll
    for (int tm = 0; tm < 2; tm++) {
        #pragma unroll
        for (int tn = 0; tn < 4; tn++) {
            int r = rbase + tm * 16;
            int n = nb0 + tn * 8;
            float2 v0 = make_float2(acc[tm][tn][0], acc[tm][tn][1]);
            float2 v1 = make_float2(acc[tm][tn][2], acc[tm][tn][3]);
            if (MODE == 1) {
                float d0 = Dv[n], d1 = Dv[n + 1];
                float2 x0 = *(const float2*)&skipX[(size_t)r * 512 + n];
                float2 x1 = *(const float2*)&skipX[(size_t)(r + 8) * 512 + n];
                v0.x = fmaf(d0, x0.x, v0.x); v0.y = fmaf(d1, x0.y, v0.y);
                v1.x = fmaf(d0, x1.x, v1.x); v1.y = fmaf(d1, x1.y, v1.y);
            }
            *(float2*)&Co[(size_t)r * 512 + n]       = v0;
            *(float2*)&Co[(size_t)(r + 8) * 512 + n] = v1;
        }
    }
}

// ---- launch ----
extern "C" void kernel_launch(void* const* d_in, const int* in_sizes, int n_in,
                              void* d_out, int out_size) {
    const float* x       = (const float*)d_in[0];
    const float* Lre     = (const float*)d_in[1];
    const float* Lim     = (const float*)d_in[2];
    const float* B       = (const float*)d_in[3];
    const float* C       = (const float*)d_in[4];
    const float* D       = (const float*)d_in[5];
    const float* logstep = (const float*)d_in[6];
    float* out = (float*)d_out;

    static int attr_done = 0;
    if (!attr_done) {
        cudaFuncSetAttribute(gemm_kernel<0>, cudaFuncAttributeMaxDynamicSharedMemorySize, GSMEM);
        cudaFuncSetAttribute(gemm_kernel<1>, cudaFuncAttributeMaxDynamicSharedMemorySize, GSMEM);
        attr_done = 1;
    }

    prep1_kernel<<<1, 256>>>(Lre, Lim, logstep);
    prep2_kernel<<<256, 256>>>(B, C);
    convx_kernel<<<2048, 256>>>(x);

    dim3 gg(HD / 64, MROWS / 128);   // (8, 256)
    gemm_kernel<0><<<gg, 256, GSMEM>>>(nullptr, nullptr, nullptr);

    scan1_kernel<<<(BSZ * NCH * PD) / 256, 256>>>();
    scan2_kernel<<<BSZ, PD>>>();
    convxs_kernel<<<(BSZ * NCH * PD) / 256, 256>>>();

    gemm_kernel<1><<<gg, 256, GSMEM>>>(x, out, D);
}

// round 15
// speedup vs baseline: 1.1533x; 1.1533x over previous
#include <cuda_runtime.h>
#include <cuda_fp16.h>
#include <math.h>
#include <stdint.h>

#define HD 512
#define PD 256
#define LD 4096
#define BSZ 8
#define MROWS (BSZ*LD)      // 32768
#define CH 64
#define NCH (LD/CH)         // 64

// ---- device scratch (no allocation allowed) ----
__device__ __align__(16) float g_Bu[(size_t)MROWS*HD];        // 64 MB fp32
__device__ __align__(16) __half g_Ah[(size_t)MROWS*HD];       // 32 MB [m][k]
__device__ __align__(16) __half g_W1h[HD*HD];                 // [n][k] fp16
__device__ __align__(16) __half g_W2h[HD*HD];
__device__ float2 g_lambda[PD];
__device__ float2 g_lamS[PD];
__device__ float2 g_coef[PD];
__device__ float2 g_bout [BSZ*NCH*PD];
__device__ float2 g_carry[BSZ*NCH*PD];

// ---- PTX helpers ----
__device__ __forceinline__ uint32_t s2u(const void* p) {
    uint32_t a;
    asm("{ .reg .u64 t; cvta.to.shared.u64 t, %1; cvt.u32.u64 %0, t; }" : "=r"(a) : "l"(p));
    return a;
}
__device__ __forceinline__ void cp16(uint32_t dst, const void* src) {
    asm volatile("cp.async.cg.shared.global [%0], [%1], 16;" :: "r"(dst), "l"(src) : "memory");
}
__device__ __forceinline__ void ldm_x4(uint32_t* r, uint32_t addr) {
    asm volatile("ldmatrix.sync.aligned.m8n8.x4.shared.b16 {%0,%1,%2,%3}, [%4];"
                 : "=r"(r[0]), "=r"(r[1]), "=r"(r[2]), "=r"(r[3]) : "r"(addr));
}
__device__ __forceinline__ void mma16816(float* d, const uint32_t* a, uint32_t b0, uint32_t b1) {
    asm volatile("mma.sync.aligned.m16n8k16.row.col.f32.f16.f16.f32 "
                 "{%0,%1,%2,%3}, {%4,%5,%6,%7}, {%8,%9}, {%0,%1,%2,%3};"
                 : "+f"(d[0]), "+f"(d[1]), "+f"(d[2]), "+f"(d[3])
                 : "r"(a[0]), "r"(a[1]), "r"(a[2]), "r"(a[3]), "r"(b0), "r"(b1));
}

// swizzled plane layout: chunk ch (16B of k), row r -> byte offset
// XOR kills the 8-way bank conflict on cp.async stores while keeping
// ldmatrix reads conflict-free (8 rows x 16B still cover all 32 banks).
#define SWZ(ch, r) (((((uint32_t)(ch)) * 128u + (uint32_t)(r)) * 16u) ^ ((((uint32_t)(ch)) & 7u) * 16u))

// ---- prep: discretization ----
__global__ void prep1_kernel(const float* __restrict__ Lre,
                             const float* __restrict__ Lim,
                             const float* __restrict__ logstep) {
    int p = threadIdx.x;
    if (p >= PD) return;
    double lre = (double)Lre[p], lim = (double)Lim[p];
    double st  = exp((double)logstep[p]);
    double ar = lre * st, ai = lim * st;
    double er = exp(ar);
    double lr = er * cos(ai), li = er * sin(ai);
    g_lambda[p] = make_float2((float)lr, (float)li);
    double eS = exp(ar * (double)CH);
    g_lamS[p]  = make_float2((float)(eS * cos(ai * (double)CH)),
                             (float)(eS * sin(ai * (double)CH)));
    double nr = lr - 1.0, ni = li;
    double d2 = lre * lre + lim * lim;
    g_coef[p] = make_float2((float)((nr * lre + ni * lim) / d2),
                            (float)((ni * lre - nr * lim) / d2));
}

// weight assembly: directly write transposed fp16 [n][k]
__global__ void prep2_kernel(const float* __restrict__ B,
                             const float* __restrict__ C) {
    int tot = HD * HD;
    for (int idx = blockIdx.x * blockDim.x + threadIdx.x;
         idx < 2 * tot; idx += gridDim.x * blockDim.x) {
        if (idx < tot) {
            int n = idx >> 9, k = idx & 511;
            int p = n >> 1;
            float2 c = g_coef[p];
            float b0 = B[((size_t)p * HD + k) * 2 + 0];
            float b1 = B[((size_t)p * HD + k) * 2 + 1];
            float v = (n & 1) ? fmaf(c.x, b1,  c.y * b0)
                              : fmaf(c.x, b0, -c.y * b1);
            g_W1h[n * 512 + k] = __float2half_rn(v);
        } else {
            int j = idx - tot;
            int n = j >> 9, k = j & 511;
            int p = k >> 1;
            float cv = C[((size_t)n * PD + p) * 2 + (k & 1)];
            float v = (k & 1) ? (-2.0f * cv) : (2.0f * cv);
            g_W2h[n * 512 + k] = __float2half_rn(v);
        }
    }
}

// x fp32 -> Ah fp16 row-major
__global__ void convx_kernel(const float* __restrict__ x) {
    size_t nseg = (size_t)MROWS * 64;
    for (size_t g = (size_t)blockIdx.x * blockDim.x + threadIdx.x;
         g < nseg; g += (size_t)gridDim.x * blockDim.x) {
        size_t m = g >> 6; int k8 = (int)(g & 63);
        const float4* s4 = (const float4*)(x + m * 512 + k8 * 8);
        float4 a = s4[0], b = s4[1];
        __half2 h0 = __floats2half2_rn(a.x, a.y);
        __half2 h1 = __floats2half2_rn(a.z, a.w);
        __half2 h2 = __floats2half2_rn(b.x, b.y);
        __half2 h3 = __floats2half2_rn(b.z, b.w);
        *(uint4*)(g_Ah + m * 512 + k8 * 8) =
            make_uint4(*(uint32_t*)&h0, *(uint32_t*)&h1, *(uint32_t*)&h2, *(uint32_t*)&h3);
    }
}

// ---- chunked complex scan (pass 1 read-only) ----
__global__ void scan1_kernel() {
    int tid = blockIdx.x * 256 + threadIdx.x;
    int p = tid & (PD - 1);
    int c = (tid >> 8) & (NCH - 1);
    int b = tid >> 14;
    float2 lam = g_lambda[p];
    float xr = 0.f, xi = 0.f;
    const float2* base = (const float2*)g_Bu + ((size_t)(b * LD + c * CH)) * PD + p;
    #pragma unroll 8
    for (int j = 0; j < CH; j++) {
        float2 v = base[(size_t)j * PD];
        float nr = fmaf(lam.x, xr, fmaf(-lam.y, xi, v.x));
        float ni = fmaf(lam.y, xr, fmaf( lam.x, xi, v.y));
        xr = nr; xi = ni;
    }
    g_bout[(b * NCH + c) * PD + p] = make_float2(xr, xi);
}

__global__ void scan2_kernel() {
    int b = blockIdx.x;
    int p = threadIdx.x;
    float2 lS = g_lamS[p];
    float cr = 0.f, ci = 0.f;
    for (int c = 0; c < NCH; c++) {
        int idx = (b * NCH + c) * PD + p;
        g_carry[idx] = make_float2(cr, ci);
        float2 bo = g_bout[idx];
        float nr = fmaf(lS.x, cr, fmaf(-lS.y, ci, bo.x));
        float ni = fmaf(lS.y, cr, fmaf( lS.x, ci, bo.y));
        cr = nr; ci = ni;
    }
}

// re-run local recurrence from carry + fp16 convert of xs -> Ah
__global__ void convxs_kernel() {
    int tid = blockIdx.x * 256 + threadIdx.x;
    int p = tid & (PD - 1);
    int c = (tid >> 8) & (NCH - 1);
    int b = tid >> 14;
    float2 lam = g_lambda[p];
    float2 car = g_carry[(b * NCH + c) * PD + p];
    float tr = car.x, ti = car.y;
    const float2* src = (const float2*)g_Bu + ((size_t)(b * LD + c * CH)) * PD + p;
    size_t m0 = (size_t)b * LD + c * CH;
    #pragma unroll 4
    for (int j = 0; j < CH; j++) {
        float2 v = src[(size_t)j * PD];
        float nr = fmaf(lam.x, tr, fmaf(-lam.y, ti, v.x));
        float ni = fmaf(lam.y, tr, fmaf( lam.x, ti, v.y));
        tr = nr; ti = ni;
        __half2 H = __floats2half2_rn(tr, ti);
        *(uint32_t*)(g_Ah + (m0 + j) * 512 + 2 * p) = *(uint32_t*)&H;
    }
}

// ---- HMMA fp16 GEMM: C[128,128] per CTA, K = 512, BK = 64 ----
// MODE 0: g_Bu = x(Ah) @ W1h ; MODE 1: out = xs(Ah) @ W2h + D*x
#define NSTG 3
#define STGB 32768            // A 16KB + B 16KB per stage
#define GSMEM (NSTG*STGB)     // 96 KB
#define NITER 8               // 512 / 64

template <int MODE>
__global__ void __launch_bounds__(256, 2)
gemm_kernel(const float* __restrict__ skipX,
            float* __restrict__ Cext,
            const float* __restrict__ Dv) {
    extern __shared__ __align__(1024) unsigned char smem[];
    uint32_t sa = s2u(smem);
    int tid = threadIdx.x, wid = tid >> 5, lane = tid & 31;
    int row0 = blockIdx.y * 128, col0 = blockIdx.x * 128;
    float* Co = MODE ? Cext : g_Bu;
    const __half* Wh = MODE ? g_W2h : g_W1h;

    // loader: 16B chunk lc (0..7), base row lr (0..31), 4 row-passes
    int lc = tid & 7, lr = tid >> 3;

    auto load_stage = [&](int st, int it) {
        int k0 = it * 64 + lc * 8;
        uint32_t sA = sa + st * STGB;
        uint32_t sB = sA + 16384;
        #pragma unroll
        for (int i = 0; i < 4; i++) {
            int r = lr + i * 32;
            cp16(sA + SWZ(lc, r), g_Ah + (size_t)(row0 + r) * 512 + k0);
            cp16(sB + SWZ(lc, r), Wh + (size_t)(col0 + r) * 512 + k0);
        }
        asm volatile("cp.async.commit_group;" ::: "memory");
    };

    float acc[2][8][4];
    #pragma unroll
    for (int i = 0; i < 2; i++)
        #pragma unroll
        for (int j = 0; j < 8; j++)
            #pragma unroll
            for (int q = 0; q < 4; q++) acc[i][j][q] = 0.f;

    load_stage(0, 0);
    load_stage(1, 1);

    int wm = (wid & 3) * 32, wn = (wid >> 2) * 64;
    int lrow = lane & 15, lhalf = lane >> 4;

    #pragma unroll 1
    for (int it = 0; it < NITER; it++) {
        int st = it % NSTG;
        asm volatile("cp.async.wait_group 1;" ::: "memory");
        __syncthreads();
        if (it + 2 < NITER) load_stage((it + 2) % NSTG, it + 2);
        else asm volatile("cp.async.commit_group;" ::: "memory");

        uint32_t sA = sa + st * STGB, sB = sA + 16384;
        #pragma unroll
        for (int s = 0; s < 4; s++) {
            int ch = s * 2 + lhalf;
            uint32_t a[2][4], b[4][4];
            #pragma unroll
            for (int tm = 0; tm < 2; tm++)
                ldm_x4(a[tm], sA + SWZ(ch, wm + tm * 16 + lrow));
            #pragma unroll
            for (int tp = 0; tp < 4; tp++)
                ldm_x4(b[tp], sB + SWZ(ch, wn + tp * 16 + lrow));
            #pragma unroll
            for (int tm = 0; tm < 2; tm++)
                #pragma unroll
                for (int tn = 0; tn < 8; tn++) {
                    int tp = tn >> 1, w = tn & 1;
                    mma16816(acc[tm][tn], a[tm], b[tp][w], b[tp][w + 2]);
                }
        }
    }

    // epilogue: d-frag lane mapping: rows l>>2 (+8), cols (l&3)*2 (+1)
    int rbase = row0 + wm + (lane >> 2);
    int nb0 = col0 + wn + (lane & 3) * 2;
    #pragma unroll
    for (int tm = 0; tm < 2; tm++) {
        #pragma unroll
        for (int tn = 0; tn < 8; tn++) {
            int r = rbase + tm * 16;
            int n = nb0 + tn * 8;
            float2 v0 = make_float2(acc[tm][tn][0], acc[tm][tn][1]);
            float2 v1 = make_float2(acc[tm][tn][2], acc[tm][tn][3]);
            if (MODE == 1) {
                float d0 = Dv[n], d1 = Dv[n + 1];
                float2 x0 = *(const float2*)&skipX[(size_t)r * 512 + n];
                float2 x1 = *(const float2*)&skipX[(size_t)(r + 8) * 512 + n];
                v0.x = fmaf(d0, x0.x, v0.x); v0.y = fmaf(d1, x0.y, v0.y);
                v1.x = fmaf(d0, x1.x, v1.x); v1.y = fmaf(d1, x1.y, v1.y);
            }
            *(float2*)&Co[(size_t)r * 512 + n]       = v0;
            *(float2*)&Co[(size_t)(r + 8) * 512 + n] = v1;
        }
    }
}

// ---- launch ----
extern "C" void kernel_launch(void* const* d_in, const int* in_sizes, int n_in,
                              void* d_out, int out_size) {
    const float* x       = (const float*)d_in[0];
    const float* Lre     = (const float*)d_in[1];
    const float* Lim     = (const float*)d_in[2];
    const float* B       = (const float*)d_in[3];
    const float* C       = (const float*)d_in[4];
    const float* D       = (const float*)d_in[5];
    const float* logstep = (const float*)d_in[6];
    float* out = (float*)d_out;

    static int attr_done = 0;
    if (!attr_done) {
        cudaFuncSetAttribute(gemm_kernel<0>, cudaFuncAttributeMaxDynamicSharedMemorySize, GSMEM);
        cudaFuncSetAttribute(gemm_kernel<1>, cudaFuncAttributeMaxDynamicSharedMemorySize, GSMEM);
        attr_done = 1;
    }

    prep1_kernel<<<1, 256>>>(Lre, Lim, logstep);
    prep2_kernel<<<256, 256>>>(B, C);
    convx_kernel<<<2048, 256>>>(x);

    dim3 gg(HD / 128, MROWS / 128);   // (4, 256)
    gemm_kernel<0><<<gg, 256, GSMEM>>>(nullptr, nullptr, nullptr);

    scan1_kernel<<<(BSZ * NCH * PD) / 256, 256>>>();
    scan2_kernel<<<BSZ, PD>>>();
    convxs_kernel<<<(BSZ * NCH * PD) / 256, 256>>>();

    gemm_kernel<1><<<gg, 256, GSMEM>>>(x, out, D);
}